// round 3
// baseline (speedup 1.0000x reference)
#include <cuda_runtime.h>
#include <cuda_bf16.h>
#include <math.h>

// RankingLoss: B=65536 rows, C=1024 classes, float32 scores, int32 labels.
// loss = mean_b [ log1p(exp(2*(2.5 - s_pos))) + log1p(exp(2*(0.5 + s_neg))) ]
//   s_pos = scores[b, label[b]]
//   s_neg = max_{c != label} scores[b,c]   (0 if label == 0)

#define NUM_B 65536
#define NUM_C 1024
#define WARPS_PER_BLOCK 8

__device__ double g_acc = 0.0;
__device__ unsigned int g_done = 0;

__device__ __forceinline__ float softplus_g(float t) {
    return (t > 20.0f) ? t : log1pf(__expf(t));
}

__global__ void __launch_bounds__(WARPS_PER_BLOCK * 32)
ranking_loss_kernel(const float* __restrict__ scores,
                    const int* __restrict__ labels,
                    float* __restrict__ out)
{
    const int lane = threadIdx.x & 31;
    const int warp = threadIdx.x >> 5;
    const int row  = blockIdx.x * WARPS_PER_BLOCK + warp;

    const int lbl    = labels[row];
    const int lblf4  = lbl >> 2;      // float4 index holding the label column
    const int lblsub = lbl & 3;       // element within that float4

    const float4* __restrict__ rp =
        (const float4*)(scores + (size_t)row * NUM_C);

    // ---- Front-batch ALL loads: 8 independent LDG.128 in flight (MLP=8). ----
    float4 v[8];
    #pragma unroll
    for (int w = 0; w < 8; ++w)
        v[w] = __ldcs(&rp[w * 32 + lane]);   // streaming: read-once data

    // ---- Compute: one label-compare per float4, not per element. ----
    float vmax = -INFINITY;
    float spos = -INFINITY;
    #pragma unroll
    for (int w = 0; w < 8; ++w) {
        float a0 = v[w].x, a1 = v[w].y, a2 = v[w].z, a3 = v[w].w;
        if (w * 32 + lane == lblf4) {        // rare: 1 lane-iter per row
            if (lblsub == 0) { spos = a0; a0 = -INFINITY; }
            else if (lblsub == 1) { spos = a1; a1 = -INFINITY; }
            else if (lblsub == 2) { spos = a2; a2 = -INFINITY; }
            else                  { spos = a3; a3 = -INFINITY; }
        }
        vmax = fmaxf(vmax, fmaxf(fmaxf(a0, a1), fmaxf(a2, a3)));
    }

    // Warp tree reduction: max for vmax, max for spos (one lane holds spos).
    #pragma unroll
    for (int o = 16; o > 0; o >>= 1) {
        vmax = fmaxf(vmax, __shfl_xor_sync(0xffffffffu, vmax, o));
        spos = fmaxf(spos, __shfl_xor_sync(0xffffffffu, spos, o));
    }

    float row_loss = 0.0f;
    if (lane == 0) {
        const float s_neg = (lbl == 0) ? 0.0f : vmax;
        row_loss = softplus_g(2.0f * (2.5f - spos))
                 + softplus_g(2.0f * (0.5f + s_neg));
    }

    // Block reduction of the 8 per-warp row losses.
    __shared__ float s_part[WARPS_PER_BLOCK];
    if (lane == 0) s_part[warp] = row_loss;
    __syncthreads();

    if (threadIdx.x == 0) {
        float blk = 0.0f;
        #pragma unroll
        for (int i = 0; i < WARPS_PER_BLOCK; ++i) blk += s_part[i];
        atomicAdd(&g_acc, (double)blk);
        __threadfence();
        const unsigned int ticket = atomicAdd(&g_done, 1u);
        if (ticket == gridDim.x - 1) {
            *out = (float)(g_acc / (double)NUM_B);
            g_acc = 0.0;
            g_done = 0;
        }
    }
}

extern "C" void kernel_launch(void* const* d_in, const int* in_sizes, int n_in,
                              void* d_out, int out_size)
{
    const float* scores = (const float*)d_in[0];
    const int*   labels = (const int*)d_in[1];
    float*       out    = (float*)d_out;

    const int grid = NUM_B / WARPS_PER_BLOCK;   // 8192
    ranking_loss_kernel<<<grid, WARPS_PER_BLOCK * 32>>>(scores, labels, out);
}